// round 12
// baseline (speedup 1.0000x reference)
#include <cuda_runtime.h>
#include <cuda_fp16.h>
#include <math.h>
#include <stdint.h>

#define TOK   4096
#define DIM   1024
#define NH    16
#define HDIM  64
#define NE    8
#define FF    4096
#define SEQ   1024

// ---------------- scratch (device globals; no allocations) ----------------
__device__ float  g_xn  [TOK * DIM];                 // exact rmsnorm output (router)
__device__ __half g_xnh [TOK * DIM];                 // half rmsnorm output (GEMM A)
__device__ __half g_qkvh[(size_t)3 * TOK * DIM];     // packed q,k,v (half)
__device__ __half g_attnh[TOK * DIM];                // flash out (half)
__device__ __half g_hgh [(size_t)2 * TOK * FF];      // MoE hidden (half)
__device__ float  g_ymid[(size_t)2 * TOK * DIM];
// half weights (converted per launch)
__device__ __half g_wqkvh[(size_t)3 * DIM * DIM];
__device__ __half g_woh  [(size_t)DIM * DIM];
__device__ __half g_w1h  [(size_t)NE * FF * DIM];
__device__ __half g_w3h  [(size_t)NE * FF * DIM];
__device__ __half g_w2h  [(size_t)NE * DIM * FF];
__device__ int   g_counts[NE];
__device__ int   g_basev [NE + 1];
__device__ int   g_cursor[NE];
__device__ int   g_tokl [2 * TOK];
__device__ float g_agate[2 * TOK];
__device__ int   g_slot [2 * TOK];
__device__ int   g_texp [2 * TOK];
__device__ float g_tgate[2 * TOK];

// ================= helpers =================
__device__ __forceinline__ uint32_t smem_u32(const void* p) {
    uint32_t a;
    asm("{ .reg .u64 t; cvta.to.shared.u64 t, %1; cvt.u32.u64 %0, t; }" : "=r"(a) : "l"(p));
    return a;
}
__device__ __forceinline__ void mma16(float* d, const uint32_t* a, const uint32_t* b) {
    asm volatile(
        "mma.sync.aligned.m16n8k16.row.col.f32.f16.f16.f32 "
        "{%0,%1,%2,%3}, {%4,%5,%6,%7}, {%8,%9}, {%0,%1,%2,%3};"
        : "+f"(d[0]), "+f"(d[1]), "+f"(d[2]), "+f"(d[3])
        : "r"(a[0]), "r"(a[1]), "r"(a[2]), "r"(a[3]), "r"(b[0]), "r"(b[1]));
}
#define LDSM4(R, addr) \
    asm volatile("ldmatrix.sync.aligned.m8n8.x4.shared.b16 {%0,%1,%2,%3}, [%4];" \
        : "=r"((R)[0]), "=r"((R)[1]), "=r"((R)[2]), "=r"((R)[3]) : "r"(addr))
#define LDSM4T(R, addr) \
    asm volatile("ldmatrix.sync.aligned.m8n8.x4.trans.shared.b16 {%0,%1,%2,%3}, [%4];" \
        : "=r"((R)[0]), "=r"((R)[1]), "=r"((R)[2]), "=r"((R)[3]) : "r"(addr))
__device__ __forceinline__ void cpa16(uint32_t dst, const void* src, int sz) {
    asm volatile("cp.async.cg.shared.global [%0], [%1], 16, %2;"
                 :: "r"(dst), "l"(src), "r"(sz) : "memory");
}
#define CPA_COMMIT() asm volatile("cp.async.commit_group;" ::: "memory")

// ---------------- weight fp32 -> fp16 conversion ----------------
__global__ void cvt_k(const float* __restrict__ s, __half* __restrict__ d, int n) {
    int i = (blockIdx.x * 256 + threadIdx.x) * 8;
    if (i >= n) return;
    float4 a = *(const float4*)(s + i);
    float4 b = *(const float4*)(s + i + 4);
    __half2 h0 = __floats2half2_rn(a.x, a.y);
    __half2 h1 = __floats2half2_rn(a.z, a.w);
    __half2 h2 = __floats2half2_rn(b.x, b.y);
    __half2 h3 = __floats2half2_rn(b.z, b.w);
    uint4 o;
    o.x = *(uint32_t*)&h0; o.y = *(uint32_t*)&h1;
    o.z = *(uint32_t*)&h2; o.w = *(uint32_t*)&h3;
    *(uint4*)(d + i) = o;
}

// ================= unified fp16 mma GEMM =================
// 256 threads, 8 warps, BK=32, 4-stage cp.async pipeline.
// MODE 0/2/3: block tile 128(M) x 128(N), warps 2M x 4N, warp tile 64x32.
// MODE 1:     block tile 128(M) x  64(N), warps 4M x 2N, warp tile 32x32 (dual acc).
// MODE 0: Cf = A @ Bw^T + Res           (wo projection, fp32 out)
// MODE 1: hg = silu(X@W1^T)*(X@W3^T)    (gathered rows, half out)
// MODE 2: ymid = gate * (hg @ W2^T)     (fp32 out)
// MODE 3: fused QKV (combined weights, half out packed)
template<int MODE>
__global__ __launch_bounds__(256, 2)
void mma_gemm(const __half* __restrict__ A, const __half* __restrict__ Bw,
              const __half* __restrict__ B3w, const float* __restrict__ Res,
              float* __restrict__ Cf, __half* __restrict__ Ch,
              int M, int N, int Kd)
{
    constexpr int MI = (MODE == 1) ? 2 : 4;       // m16 frags per warp
    constexpr int BN = (MODE == 1) ? 64 : 128;    // block N
    constexpr int STAGES = 4;
    constexpr uint32_t ASTG = 128 * 80;           // bytes (128 rows x 40 halves)
    constexpr uint32_t BSTG = BN * 80;
    extern __shared__ char smraw[];
    uint32_t smA = smem_u32(smraw);
    uint32_t smB  = smA + STAGES * ASTG;
    uint32_t smB3 = smB + STAGES * BSTG;
    __shared__ int stok[128];

    int tid = threadIdx.x;
    int lane = tid & 31, wid = tid >> 5;
    int wm = (MODE == 1) ? (wid & 3) * 32 : (wid & 1) * 64;
    int wn = (MODE == 1) ? (wid >> 2) * 32 : (wid >> 1) * 32;
    int gq = lane >> 2, tq = lane & 3;

    int e = blockIdx.z;
    int cnt, base;
    const __half* b1p;
    const __half* b3p = nullptr;
    int n0 = blockIdx.x * BN;
    int which = 0;
    if (MODE == 0)      { cnt = M; base = 0; b1p = Bw; }
    else if (MODE == 1) { cnt = g_counts[e]; base = g_basev[e];
                          b1p = Bw  + (size_t)e * FF * DIM;
                          b3p = B3w + (size_t)e * FF * DIM; }
    else if (MODE == 2) { cnt = g_counts[e]; base = g_basev[e];
                          b1p = Bw + (size_t)e * DIM * FF; }
    else                { cnt = M; base = 0;
                          which = n0 >> 10; n0 &= 1023;
                          b1p = Bw + ((size_t)which << 10) * Kd; }
    if ((int)blockIdx.y * 128 >= cnt) return;

    const int NT = Kd >> 5;
    const int maxrow = 2 * TOK - 1;

    // ldmatrix per-lane addressing (stride 40 halves = 80B)
    uint32_t aA0 = smA + (uint32_t)((wm + (lane & 15)) * 80 + (lane >> 4) * 16);
    int lrB = (lane & 7) + ((lane >> 4) << 3);
    uint32_t lcB = ((lane >> 3) & 1) * 16;
    uint32_t aB0  = smB  + (uint32_t)((wn + lrB) * 80) + lcB;
    uint32_t aB30 = smB3 + (uint32_t)((wn + lrB) * 80) + lcB;

    for (int rt = blockIdx.y; rt * 128 < cnt; rt += gridDim.y) {
        int m0 = rt * 128;
        if (MODE == 1) {
            if (tid < 128) {
                int lr = m0 + tid;
                stok[tid] = (lr < cnt) ? g_tokl[base + lr] : -1;
            }
            __syncthreads();
        }

        auto load_tile = [&](int st, int kt) {
            int k0 = kt << 5;
#pragma unroll
            for (int i = 0; i < 2; i++) {           // A: 128 rows x 4 chunks(16B)
                int f = i * 256 + tid;
                int row = f >> 2, c = f & 3;
                uint32_t d = smA + (uint32_t)st * ASTG + (uint32_t)(row * 80 + c * 16);
                const __half* s;
                int sz = 16;
                if (MODE == 0 || MODE == 3) {
                    s = A + (size_t)(m0 + row) * Kd + k0 + c * 8;
                } else if (MODE == 1) {
                    int t = stok[row];
                    if (t < 0) { t = 0; sz = 0; }
                    s = g_xnh + (size_t)t * DIM + k0 + c * 8;
                } else {
                    int ar = base + m0 + row;
                    if (ar > maxrow) ar = maxrow;
                    s = g_hgh + (size_t)ar * FF + k0 + c * 8;
                }
                cpa16(d, s, sz);
            }
#pragma unroll
            for (int i = 0; i < BN / 64; i++) {     // B: BN rows x 4 chunks
                int f = i * 256 + tid;
                int row = f >> 2, c = f & 3;
                uint32_t off = (uint32_t)(row * 80 + c * 16);
                cpa16(smB + (uint32_t)st * BSTG + off,
                      b1p + (size_t)(n0 + row) * Kd + k0 + c * 8, 16);
                if (MODE == 1)
                    cpa16(smB3 + (uint32_t)st * BSTG + off,
                          b3p + (size_t)(n0 + row) * Kd + k0 + c * 8, 16);
            }
        };

        float acc[MI][4][4] = {};
        float acc3[(MODE == 1) ? 2 : 1][(MODE == 1) ? 4 : 1][4] = {};

#pragma unroll
        for (int i = 0; i < STAGES - 1; i++) { load_tile(i, i); CPA_COMMIT(); }

        for (int kt = 0; kt < NT; kt++) {
            asm volatile("cp.async.wait_group 2;" ::: "memory");
            __syncthreads();
            int st = kt & 3;
            {
                int nst = kt + 3;
                if (nst < NT) load_tile(nst & 3, nst);
                CPA_COMMIT();
            }
            uint32_t sA = (uint32_t)st * ASTG;
            uint32_t sB = (uint32_t)st * BSTG;
#pragma unroll
            for (int kg = 0; kg < 2; kg++) {
                uint32_t af[MI][4];
#pragma unroll
                for (int mi = 0; mi < MI; mi++)
                    LDSM4(af[mi], aA0 + sA + mi * 1280 + kg * 32);
                uint32_t bf[4][2];
#pragma unroll
                for (int j = 0; j < 2; j++) {
                    uint32_t t4[4];
                    LDSM4(t4, aB0 + sB + j * 1280 + kg * 32);
                    bf[2 * j][0] = t4[0]; bf[2 * j][1] = t4[1];
                    bf[2 * j + 1][0] = t4[2]; bf[2 * j + 1][1] = t4[3];
                }
                if (MODE == 1) {
                    uint32_t b3f[4][2];
#pragma unroll
                    for (int j = 0; j < 2; j++) {
                        uint32_t t4[4];
                        LDSM4(t4, aB30 + sB + j * 1280 + kg * 32);
                        b3f[2 * j][0] = t4[0]; b3f[2 * j][1] = t4[1];
                        b3f[2 * j + 1][0] = t4[2]; b3f[2 * j + 1][1] = t4[3];
                    }
#pragma unroll
                    for (int mi = 0; mi < MI; mi++)
#pragma unroll
                        for (int ni = 0; ni < 4; ni++) {
                            mma16(acc[mi][ni], af[mi], bf[ni]);
                            mma16(acc3[mi][ni], af[mi], b3f[ni]);
                        }
                } else {
#pragma unroll
                    for (int mi = 0; mi < MI; mi++)
#pragma unroll
                        for (int ni = 0; ni < 4; ni++)
                            mma16(acc[mi][ni], af[mi], bf[ni]);
                }
            }
        }

        // ---------------- epilogue ----------------
        if (MODE == 0) {
#pragma unroll
            for (int mi = 0; mi < MI; mi++) {
                int r0 = m0 + wm + mi * 16 + gq;
#pragma unroll
                for (int ni = 0; ni < 4; ni++) {
                    int c0 = n0 + wn + ni * 8 + 2 * tq;
                    float2 v0 = make_float2(acc[mi][ni][0], acc[mi][ni][1]);
                    float2 v1 = make_float2(acc[mi][ni][2], acc[mi][ni][3]);
                    float2 q0 = *(const float2*)&Res[(size_t)r0 * N + c0];
                    float2 q1 = *(const float2*)&Res[(size_t)(r0 + 8) * N + c0];
                    v0.x += q0.x; v0.y += q0.y; v1.x += q1.x; v1.y += q1.y;
                    *(float2*)&Cf[(size_t)r0 * N + c0] = v0;
                    *(float2*)&Cf[(size_t)(r0 + 8) * N + c0] = v1;
                }
            }
        } else if (MODE == 3) {
            __half* Co = Ch + (size_t)which * TOK * DIM;
#pragma unroll
            for (int mi = 0; mi < MI; mi++) {
                int r0 = m0 + wm + mi * 16 + gq;
#pragma unroll
                for (int ni = 0; ni < 4; ni++) {
                    int c0 = n0 + wn + ni * 8 + 2 * tq;
                    *(__half2*)&Co[(size_t)r0 * N + c0] =
                        __floats2half2_rn(acc[mi][ni][0], acc[mi][ni][1]);
                    *(__half2*)&Co[(size_t)(r0 + 8) * N + c0] =
                        __floats2half2_rn(acc[mi][ni][2], acc[mi][ni][3]);
                }
            }
        } else if (MODE == 1) {
#pragma unroll
            for (int mi = 0; mi < MI; mi++) {
#pragma unroll
                for (int half = 0; half < 2; half++) {
                    int rl = m0 + wm + mi * 16 + gq + half * 8;
                    if (rl < cnt) {
                        __half* op = g_hgh + (size_t)(base + rl) * FF;
#pragma unroll
                        for (int ni = 0; ni < 4; ni++) {
                            int c0 = n0 + wn + ni * 8 + 2 * tq;
                            float z0 = acc[mi][ni][half * 2];
                            float z1 = acc[mi][ni][half * 2 + 1];
                            float h0 = (z0 / (1.f + __expf(-z0))) * acc3[mi][ni][half * 2];
                            float h1 = (z1 / (1.f + __expf(-z1))) * acc3[mi][ni][half * 2 + 1];
                            *(__half2*)&op[c0] = __floats2half2_rn(h0, h1);
                        }
                    }
                }
            }
        } else {
#pragma unroll
            for (int mi = 0; mi < MI; mi++) {
#pragma unroll
                for (int half = 0; half < 2; half++) {
                    int rl = m0 + wm + mi * 16 + gq + half * 8;
                    if (rl < cnt) {
                        float gate = g_agate[base + rl];
                        float* op = g_ymid + (size_t)(base + rl) * DIM;
#pragma unroll
                        for (int ni = 0; ni < 4; ni++) {
                            int c0 = n0 + wn + ni * 8 + 2 * tq;
                            *(float2*)&op[c0] = make_float2(acc[mi][ni][half * 2] * gate,
                                                            acc[mi][ni][half * 2 + 1] * gate);
                        }
                    }
                }
            }
        }
        __syncthreads();
    }
}

// ---------------- rmsnorm (exact fp32 + half copies) ----------------
__global__ void rmsnorm_k(const float* __restrict__ x, const float* __restrict__ w,
                          float* __restrict__ out, __half* __restrict__ outh) {
    int row = blockIdx.x;
    const float* xr = x + (size_t)row * DIM;
    float v[4];
    float s = 0.f;
#pragma unroll
    for (int i = 0; i < 4; i++) {
        v[i] = xr[threadIdx.x + i * 256];
        s += v[i] * v[i];
    }
    __shared__ float red[8];
#pragma unroll
    for (int o = 16; o > 0; o >>= 1) s += __shfl_xor_sync(0xffffffffu, s, o);
    if ((threadIdx.x & 31) == 0) red[threadIdx.x >> 5] = s;
    __syncthreads();
    if (threadIdx.x < 8) {
        float t = red[threadIdx.x];
#pragma unroll
        for (int o = 4; o > 0; o >>= 1) t += __shfl_xor_sync(0xffu, t, o);
        if (threadIdx.x == 0) red[0] = t;
    }
    __syncthreads();
    float scale = rsqrtf(red[0] * (1.0f / DIM) + 1e-6f);
#pragma unroll
    for (int i = 0; i < 4; i++) {
        int c = threadIdx.x + i * 256;
        float val = v[i] * scale * w[c];
        out[(size_t)row * DIM + c]  = val;
        outh[(size_t)row * DIM + c] = __float2half_rn(val);
    }
}

// ---------------- RoPE (half in/out, fp32 math) ----------------
__global__ void rope_k(__half* __restrict__ qh, __half* __restrict__ kh,
                       const float* __restrict__ fc, const float* __restrict__ fs) {
    int idx = blockIdx.x * blockDim.x + threadIdx.x;
    if (idx >= TOK * NH * (HDIM / 2)) return;
    int i = idx & 31;
    int h = (idx >> 5) & (NH - 1);
    int t = idx >> 9;
    int s = t & (SEQ - 1);
    float c = fc[s * 32 + i], sn = fs[s * 32 + i];
    size_t bse = (size_t)t * DIM + h * HDIM + 2 * i;
    float2 q2 = __half22float2(*(__half2*)&qh[bse]);
    *(__half2*)&qh[bse] = __floats2half2_rn(q2.x * c - q2.y * sn, q2.x * sn + q2.y * c);
    float2 k2 = __half22float2(*(__half2*)&kh[bse]);
    *(__half2*)&kh[bse] = __floats2half2_rn(k2.x * c - k2.y * sn, k2.x * sn + k2.y * c);
}

// ---------------- flash attention, fp16 mma, 128x64 tiles ----------------
#define FBM 128
#define FBN 64
__global__ __launch_bounds__(256, 2)
void flash_k(const __half* __restrict__ Q, const __half* __restrict__ Kp,
             const __half* __restrict__ V, __half* __restrict__ O,
             const int* __restrict__ p_causal) {
    constexpr uint32_t KVSTG = 64 * 144;          // bytes per K or V stage
    extern __shared__ char smraw[];
    __half* Qs = (__half*)smraw;                  // [128][72]
    __half* Ks = Qs + 128 * 72;                   // [2][64][72]
    __half* Vs = Ks + 2 * 64 * 72;                // [2][64][72] natural [kv][d]
    __half* Ps = Vs + 2 * 64 * 72;                // [128][72]
    float* redm = (float*)(Ps + 128 * 72);        // [2][128]
    float* reds = redm + 256;                     // [2][128]

    int qt = gridDim.x - 1 - blockIdx.x;          // heavy causal tiles first
    int h = blockIdx.y, b = blockIdx.z;
    int causal = *p_causal;
    int tid = threadIdx.x;
    int lane = tid & 31, wid = tid >> 5;
    int wm = (wid & 3) * 32;
    int side = wid >> 2;
    int wn2 = side * 32;
    int gq = lane >> 2, tq = lane & 3;
    int t0 = b * SEQ + qt * FBM;

    uint32_t sQ = smem_u32(Qs), sK = smem_u32(Ks), sV = smem_u32(Vs), sP = smem_u32(Ps);
    uint32_t aQ = sQ + (uint32_t)((wm + (lane & 15)) * 144 + (lane >> 4) * 16);
    int lrB = (lane & 7) + ((lane >> 4) << 3);
    uint32_t aK = sK + (uint32_t)((wn2 + lrB) * 144) + ((lane >> 3) & 1) * 16;
    uint32_t aP = sP + (uint32_t)((wm + (lane & 15)) * 144 + (lane >> 4) * 16);
    uint32_t aV = sV + (uint32_t)((lane & 15) * 144 + (lane >> 4) * 16);

    // Q tile: 128 rows x 8 chunks
#pragma unroll
    for (int i = 0; i < 4; i++) {
        int f = i * 256 + tid;
        int row = f >> 3, c8 = f & 7;
        cpa16(sQ + (uint32_t)(row * 144 + c8 * 16),
              Q + (size_t)(t0 + row) * DIM + h * HDIM + c8 * 8, 16);
    }

    auto load_kv = [&](int buf, int kt) {
        int k0 = b * SEQ + kt * FBN;
#pragma unroll
        for (int i = 0; i < 2; i++) {
            int f = i * 256 + tid;
            int row = f >> 3, c8 = f & 7;
            uint32_t off = (uint32_t)buf * KVSTG + (uint32_t)(row * 144 + c8 * 16);
            const __half* src = Kp + (size_t)(k0 + row) * DIM + h * HDIM + c8 * 8;
            cpa16(sK + off, src, 16);
            const __half* srcv = V + (size_t)(k0 + row) * DIM + h * HDIM + c8 * 8;
            cpa16(sV + off, srcv, 16);
        }
    };

    load_kv(0, 0);
    CPA_COMMIT();

    float m_i[2][2], l_i[2][2], oacc[2][4][4] = {};
#pragma unroll
    for (int a = 0; a < 2; a++)
#pragma unroll
        for (int c = 0; c < 2; c++) { m_i[a][c] = -1e30f; l_i[a][c] = 0.f; }

    int nkt = causal ? (2 * qt + 2) : (SEQ / FBN);
    const float scale = 0.125f;

    for (int kt = 0; kt < nkt; kt++) {
        asm volatile("cp.async.wait_group 0;" ::: "memory");
        __syncthreads();
        if (kt + 1 < nkt) { load_kv((kt + 1) & 1, kt + 1); CPA_COMMIT(); }
        uint32_t kb = (uint32_t)(kt & 1) * KVSTG;

        // S = Q @ K^T
        float sacc[2][4][4] = {};
#pragma unroll
        for (int kg = 0; kg < 4; kg++) {
            uint32_t qf[2][4];
            LDSM4(qf[0], aQ + kg * 32);
            LDSM4(qf[1], aQ + 2304 + kg * 32);
            uint32_t kf[4][2];
#pragma unroll
            for (int j = 0; j < 2; j++) {
                uint32_t t4[4];
                LDSM4(t4, aK + kb + j * 2304 + kg * 32);
                kf[2 * j][0] = t4[0]; kf[2 * j][1] = t4[1];
                kf[2 * j + 1][0] = t4[2]; kf[2 * j + 1][1] = t4[3];
            }
#pragma unroll
            for (int mi = 0; mi < 2; mi++)
#pragma unroll
                for (int ni = 0; ni < 4; ni++)
                    mma16(sacc[mi][ni], qf[mi], kf[ni]);
        }

        // scale + mask + row max
#pragma unroll
        for (int mi = 0; mi < 2; mi++) {
            int r0 = qt * FBM + wm + mi * 16 + gq;
            float h0 = -1e30f, h1 = -1e30f;
#pragma unroll
            for (int ni = 0; ni < 4; ni++) {
                int c = kt * FBN + wn2 + ni * 8 + 2 * tq;
                float* s = sacc[mi][ni];
                s[0] *= scale; s[1] *= scale; s[2] *= scale; s[3] *= scale;
                if (causal) {
                    if (c     > r0)     s[0] = -1e30f;
                    if (c + 1 > r0)     s[1] = -1e30f;
                    if (c     > r0 + 8) s[2] = -1e30f;
                    if (c + 1 > r0 + 8) s[3] = -1e30f;
                }
                h0 = fmaxf(h0, fmaxf(s[0], s[1]));
                h1 = fmaxf(h1, fmaxf(s[2], s[3]));
            }
            h0 = fmaxf(h0, __shfl_xor_sync(0xffffffffu, h0, 1));
            h0 = fmaxf(h0, __shfl_xor_sync(0xffffffffu, h0, 2));
            h1 = fmaxf(h1, __shfl_xor_sync(0xffffffffu, h1, 1));
            h1 = fmaxf(h1, __shfl_xor_sync(0xffffffffu, h1, 2));
            if (tq == 0) {
                redm[side * 128 + wm + mi * 16 + gq]     = h0;
                redm[side * 128 + wm + mi * 16 + gq + 8] = h1;
            }
        }
        __syncthreads();

        float corr[2][2];
#pragma unroll
        for (int mi = 0; mi < 2; mi++)
#pragma unroll
            for (int hf = 0; hf < 2; hf++) {
                int rl = wm + mi * 16 + gq + hf * 8;
                float mt = fmaxf(redm[rl], redm[128 + rl]);
                float mn = fmaxf(m_i[mi][hf], mt);
                corr[mi][hf] = __expf(m_i[mi][hf] - mn);
                m_i[mi][hf] = mn;
            }

        // exp + partial sums + store P (half)
        float rs[2][2] = {};
#pragma unroll
        for (int mi = 0; mi < 2; mi++) {
#pragma unroll
            for (int ni = 0; ni < 4; ni++) {
                float* s = sacc[mi][ni];
                s[0] = __expf(s[0] - m_i[mi][0]);
                s[1] = __expf(s[1] - m_i[mi][0]);
                s[2] = __expf(s[2] - m_i[mi][1]);
                s[3] = __expf(s[3] - m_i[mi][1]);
                rs[mi][0] += s[0] + s[1];
                rs[mi][1] += s[2] + s[3];
                int rloc = wm + mi * 16 + gq;
                int cloc = wn2 + ni * 8 + 2 * tq;
                *(__half2*)&Ps[rloc * 72 + cloc] = __floats2half2_rn(s[0], s[1]);
                *(__half2*)&Ps[(rloc + 8) * 72 + cloc] = __floats2half2_rn(s[2], s[3]);
            }
            rs[mi][0] += __shfl_xor_sync(0xffffffffu, rs[mi][0], 1);
            rs[mi][0] += __shfl_xor_sync(0xffffffffu, rs[mi][0], 2);
            rs[mi][1] += __shfl_xor_sync(0xffffffffu, rs[mi][1], 1);
            rs[mi][1] += __shfl_xor_sync(0xffffffffu, rs[mi][1], 2);
            if (tq == 0) {
                reds[side * 128 + wm + mi * 16 + gq]     = rs[mi][0];
                reds[side * 128 + wm + mi * 16 + gq + 8] = rs[mi][1];
            }
        }
        __syncthreads();

#pragma unroll
        for (int mi = 0; mi < 2; mi++)
#pragma unroll
            for (int hf = 0; hf < 2; hf++) {
                int rl = wm + mi * 16 + gq + hf * 8;
                l_i[mi][hf] = l_i[mi][hf] * corr[mi][hf] + reds[rl] + reds[128 + rl];
            }
#pragma unroll
        for (int mi = 0; mi < 2; mi++)
#pragma unroll
            for (int ni = 0; ni < 4; ni++) {
                oacc[mi][ni][0] *= corr[mi][0];
                oacc[mi][ni][1] *= corr[mi][0];
                oacc[mi][ni][2] *= corr[mi][1];
                oacc[mi][ni][3] *= corr[mi][1];
            }

        // O += P @ V   (V natural layout, ldmatrix.trans for B frags)
#pragma unroll
        for (int kg = 0; kg < 4; kg++) {
            uint32_t pf[2][4];
            LDSM4(pf[0], aP + kg * 32);
            LDSM4(pf[1], aP + 2304 + kg * 32);
            uint32_t vf[4][2];
#pragma unroll
            for (int j = 0; j < 2; j++) {
                uint32_t t4[4];
                LDSM4T(t4, aV + kb + kg * 2304 + (uint32_t)((wn2 + j * 16) * 2));
                vf[2 * j][0] = t4[0]; vf[2 * j][1] = t4[1];
                vf[2 * j + 1][0] = t4[2]; vf[2 * j + 1][1] = t4[3];
            }
#pragma unroll
            for (int mi = 0; mi < 2; mi++)
#pragma unroll
                for (int ni = 0; ni < 4; ni++)
                    mma16(oacc[mi][ni], pf[mi], vf[ni]);
        }
    }

    // normalize + write half
#pragma unroll
    for (int mi = 0; mi < 2; mi++) {
        float inv0 = 1.0f / l_i[mi][0];
        float inv1 = 1.0f / l_i[mi][1];
        int rl = t0 + wm + mi * 16 + gq;
#pragma unroll
        for (int ni = 0; ni < 4; ni++) {
            int d0 = h * HDIM + wn2 + ni * 8 + 2 * tq;
            *(__half2*)&O[(size_t)rl * DIM + d0] =
                __floats2half2_rn(oacc[mi][ni][0] * inv0, oacc[mi][ni][1] * inv0);
            *(__half2*)&O[(size_t)(rl + 8) * DIM + d0] =
                __floats2half2_rn(oacc[mi][ni][2] * inv1, oacc[mi][ni][3] * inv1);
        }
    }
}

// ---------------- routing ----------------
__global__ void reset_k() { if (threadIdx.x < NE) g_counts[threadIdx.x] = 0; }

__global__ void router_k(const float* __restrict__ rw, const float* __restrict__ rb) {
    int t = blockIdx.x;
    int wid = threadIdx.x >> 5, lane = threadIdx.x & 31;
    const float* x = g_xn + (size_t)t * DIM;
    const float* w = rw + (size_t)wid * DIM;
    float s = 0.f;
    for (int j = lane; j < DIM; j += 32) s += x[j] * w[j];
#pragma unroll
    for (int o = 16; o > 0; o >>= 1) s += __shfl_xor_sync(0xffffffffu, s, o);
    __shared__ float lg[NE];
    if (lane == 0) lg[wid] = s + rb[wid];
    __syncthreads();
    if (threadIdx.x == 0) {
        float v0 = -1e30f; int i0 = 0;
#pragma unroll
        for (int e = 0; e < NE; e++) if (lg[e] > v0) { v0 = lg[e]; i0 = e; }
        float v1 = -1e30f; int i1 = 0;
#pragma unroll
        for (int e = 0; e < NE; e++) if (e != i0 && lg[e] > v1) { v1 = lg[e]; i1 = e; }
        float tt = __expf(v1 - v0);
        float g0 = 1.f / (1.f + tt);
        float g1 = tt / (1.f + tt);
        g_texp[2 * t] = i0;  g_texp[2 * t + 1] = i1;
        g_tgate[2 * t] = g0; g_tgate[2 * t + 1] = g1;
        atomicAdd(&g_counts[i0], 1);
        atomicAdd(&g_counts[i1], 1);
    }
}

__global__ void prefix_k() {
    int b = 0;
    for (int e = 0; e < NE; e++) { g_basev[e] = b; g_cursor[e] = b; b += g_counts[e]; }
    g_basev[NE] = b;
}

__global__ void scatter_k() {
    int t = blockIdx.x * blockDim.x + threadIdx.x;
    if (t >= TOK) return;
#pragma unroll
    for (int r = 0; r < 2; r++) {
        int e = g_texp[2 * t + r];
        int pos = atomicAdd(&g_cursor[e], 1);
        g_tokl[pos] = t;
        g_agate[pos] = g_tgate[2 * t + r];
        g_slot[2 * t + r] = pos;
    }
}

// ---------------- final combine ----------------
__global__ void combine_k(float* __restrict__ out) {
    int idx = blockIdx.x * 256 + threadIdx.x;
    int t = idx >> 10;
    int d = idx & 1023;
    int s0 = g_slot[2 * t], s1 = g_slot[2 * t + 1];
    out[idx] = out[idx] + g_ymid[(size_t)s0 * DIM + d] + g_ymid[(size_t)s1 * DIM + d];
}

// ---------------- launch ----------------
extern "C" void kernel_launch(void* const* d_in, const int* in_sizes, int n_in,
                              void* d_out, int out_size) {
    const float* q    = (const float*)d_in[0];
    const float* fc   = (const float*)d_in[3];
    const float* fs   = (const float*)d_in[4];
    const float* attw = (const float*)d_in[5];
    const float* ffnw = (const float*)d_in[6];
    const float* wq   = (const float*)d_in[7];
    const float* wk   = (const float*)d_in[8];
    const float* wv   = (const float*)d_in[9];
    const float* wo   = (const float*)d_in[10];
    const float* rw   = (const float*)d_in[11];
    const float* rb   = (const float*)d_in[12];
    const float* w1   = (const float*)d_in[13];
    const float* w2   = (const float*)d_in[14];
    const float* w3   = (const float*)d_in[15];
    const int*   pc   = (const int*)d_in[16];
    float* out = (float*)d_out;

    float *p_xn;
    __half *p_xnh, *p_qkvh, *p_attnh;
    __half *p_wqkvh, *p_woh, *p_w1h, *p_w3h, *p_w2h;
    cudaGetSymbolAddress((void**)&p_xn, g_xn);
    cudaGetSymbolAddress((void**)&p_xnh, g_xnh);
    cudaGetSymbolAddress((void**)&p_qkvh, g_qkvh);
    cudaGetSymbolAddress((void**)&p_attnh, g_attnh);
    cudaGetSymbolAddress((void**)&p_wqkvh, g_wqkvh);
    cudaGetSymbolAddress((void**)&p_woh, g_woh);
    cudaGetSymbolAddress((void**)&p_w1h, g_w1h);
    cudaGetSymbolAddress((void**)&p_w3h, g_w3h);
    cudaGetSymbolAddress((void**)&p_w2h, g_w2h);

    const int SMEM_W  = 4 * (128 * 80) * 2;   // modes 0/2/3: A(128) + B(128) = 81920
    const int SMEM_G1 = 4 * (128 * 80) + 8 * (64 * 80);  // mode 1 = 81920
    const int SMEM_FL = (128 * 72 + 2 * 64 * 72 + 2 * 64 * 72 + 128 * 72) * 2 + 512 * 4;
    cudaFuncSetAttribute(mma_gemm<0>, cudaFuncAttributeMaxDynamicSharedMemorySize, SMEM_W);
    cudaFuncSetAttribute(mma_gemm<1>, cudaFuncAttributeMaxDynamicSharedMemorySize, SMEM_G1);
    cudaFuncSetAttribute(mma_gemm<2>, cudaFuncAttributeMaxDynamicSharedMemorySize, SMEM_W);
    cudaFuncSetAttribute(mma_gemm<3>, cudaFuncAttributeMaxDynamicSharedMemorySize, SMEM_W);
    cudaFuncSetAttribute(flash_k, cudaFuncAttributeMaxDynamicSharedMemorySize, SMEM_FL);

    // 0. convert weights to fp16 (per-launch, deterministic)
    const int WQN = DIM * DIM;              // 1048576
    const int WEN = NE * FF * DIM;          // 33554432
    cvt_k<<<WQN / 8 / 256, 256>>>(wq, p_wqkvh, WQN);
    cvt_k<<<WQN / 8 / 256, 256>>>(wk, p_wqkvh + (size_t)WQN, WQN);
    cvt_k<<<WQN / 8 / 256, 256>>>(wv, p_wqkvh + (size_t)2 * WQN, WQN);
    cvt_k<<<WQN / 8 / 256, 256>>>(wo, p_woh, WQN);
    cvt_k<<<WEN / 8 / 256, 256>>>(w1, p_w1h, WEN);
    cvt_k<<<WEN / 8 / 256, 256>>>(w3, p_w3h, WEN);
    cvt_k<<<WEN / 8 / 256, 256>>>(w2, p_w2h, WEN);

    // 1. attention-input rmsnorm
    rmsnorm_k<<<TOK, 256>>>(q, attw, p_xn, p_xnh);

    // 2. fused QKV projection (fp16 mma, 128x128 tiles)
    mma_gemm<3><<<dim3(3 * DIM / 128, TOK / 128), 256, SMEM_W>>>(
        p_xnh, p_wqkvh, nullptr, nullptr, nullptr, p_qkvh, TOK, DIM, DIM);

    // 3. RoPE on q,k halves
    rope_k<<<(TOK * NH * 32 + 255) / 256, 256>>>(p_qkvh, p_qkvh + (size_t)TOK * DIM, fc, fs);

    // 4. flash attention (fp16 mma)
    dim3 gfa(SEQ / 128, NH, 4);
    flash_k<<<gfa, 256, SMEM_FL>>>(p_qkvh, p_qkvh + (size_t)TOK * DIM,
                                   p_qkvh + (size_t)2 * TOK * DIM, p_attnh, pc);

    // 5. output projection + residual (fp32 out, 128x128 tiles)
    mma_gemm<0><<<dim3(DIM / 128, TOK / 128), 256, SMEM_W>>>(
        p_attnh, p_woh, nullptr, q, out, nullptr, TOK, DIM, DIM);

    // 6. ffn rmsnorm (exact for router, half for GEMMs)
    rmsnorm_k<<<TOK, 256>>>(out, ffnw, p_xn, p_xnh);

    // 7. routing (exact fp32)
    reset_k<<<1, 32>>>();
    router_k<<<TOK, 256>>>(rw, rb);
    prefix_k<<<1, 1>>>();
    scatter_k<<<TOK / 256, 256>>>();

    // 8. MoE grouped GEMMs (fp16 mma)
    mma_gemm<1><<<dim3(FF / 64, 8, NE), 256, SMEM_G1>>>(
        nullptr, p_w1h, p_w3h, nullptr, nullptr, nullptr, 0, FF, DIM);
    mma_gemm<2><<<dim3(DIM / 128, 8, NE), 256, SMEM_W>>>(
        nullptr, p_w2h, nullptr, nullptr, nullptr, nullptr, 0, DIM, FF);

    // 9. combine
    combine_k<<<TOK * DIM / 256, 256>>>(out);
}

// round 13
// speedup vs baseline: 1.5173x; 1.5173x over previous
#include <cuda_runtime.h>
#include <cuda_fp16.h>
#include <math.h>
#include <stdint.h>

#define TOK   4096
#define DIM   1024
#define NH    16
#define HDIM  64
#define NE    8
#define FF    4096
#define SEQ   1024

// ---------------- scratch (device globals; no allocations) ----------------
__device__ float  g_xn  [TOK * DIM];                 // exact rmsnorm output (router)
__device__ __half g_xnh [TOK * DIM];                 // half rmsnorm output (GEMM A)
__device__ __half g_qkvh[(size_t)3 * TOK * DIM];     // packed q,k,v (half)
__device__ __half g_attnh[TOK * DIM];                // flash out (half)
__device__ __half g_hgh [(size_t)2 * TOK * FF];      // MoE hidden (half)
__device__ __half g_ymidh[(size_t)2 * TOK * DIM];    // MoE expert outputs (half)
// half weights (converted per launch)
__device__ __half g_wqkvh[(size_t)3 * DIM * DIM];
__device__ __half g_woh  [(size_t)DIM * DIM];
__device__ __half g_w1h  [(size_t)NE * FF * DIM];
__device__ __half g_w3h  [(size_t)NE * FF * DIM];
__device__ __half g_w2h  [(size_t)NE * DIM * FF];
__device__ int   g_counts[NE];
__device__ int   g_basev [NE + 1];
__device__ int   g_cursor[NE];
__device__ int   g_tokl [2 * TOK];
__device__ float g_agate[2 * TOK];
__device__ int   g_slot [2 * TOK];
__device__ int   g_texp [2 * TOK];
__device__ float g_tgate[2 * TOK];

// ================= helpers =================
__device__ __forceinline__ uint32_t smem_u32(const void* p) {
    uint32_t a;
    asm("{ .reg .u64 t; cvta.to.shared.u64 t, %1; cvt.u32.u64 %0, t; }" : "=r"(a) : "l"(p));
    return a;
}
__device__ __forceinline__ void mma16(float* d, const uint32_t* a, const uint32_t* b) {
    asm volatile(
        "mma.sync.aligned.m16n8k16.row.col.f32.f16.f16.f32 "
        "{%0,%1,%2,%3}, {%4,%5,%6,%7}, {%8,%9}, {%0,%1,%2,%3};"
        : "+f"(d[0]), "+f"(d[1]), "+f"(d[2]), "+f"(d[3])
        : "r"(a[0]), "r"(a[1]), "r"(a[2]), "r"(a[3]), "r"(b[0]), "r"(b[1]));
}
#define LDSM4(R, addr) \
    asm volatile("ldmatrix.sync.aligned.m8n8.x4.shared.b16 {%0,%1,%2,%3}, [%4];" \
        : "=r"((R)[0]), "=r"((R)[1]), "=r"((R)[2]), "=r"((R)[3]) : "r"(addr))
#define LDSM4T(R, addr) \
    asm volatile("ldmatrix.sync.aligned.m8n8.x4.trans.shared.b16 {%0,%1,%2,%3}, [%4];" \
        : "=r"((R)[0]), "=r"((R)[1]), "=r"((R)[2]), "=r"((R)[3]) : "r"(addr))
__device__ __forceinline__ void cpa16(uint32_t dst, const void* src, int sz) {
    asm volatile("cp.async.cg.shared.global [%0], [%1], 16, %2;"
                 :: "r"(dst), "l"(src), "r"(sz) : "memory");
}
#define CPA_COMMIT() asm volatile("cp.async.commit_group;" ::: "memory")

// ---------------- weight fp32 -> fp16 conversion (3 tensors per launch) ----------------
__global__ void cvt3_k(const float* __restrict__ s0, const float* __restrict__ s1,
                       const float* __restrict__ s2,
                       __half* __restrict__ d0, __half* __restrict__ d1,
                       __half* __restrict__ d2, int n) {
    const float* s = (blockIdx.y == 0) ? s0 : (blockIdx.y == 1) ? s1 : s2;
    __half*      d = (blockIdx.y == 0) ? d0 : (blockIdx.y == 1) ? d1 : d2;
    int i = (blockIdx.x * 256 + threadIdx.x) * 8;
    if (i >= n) return;
    float4 a = *(const float4*)(s + i);
    float4 b = *(const float4*)(s + i + 4);
    __half2 h0 = __floats2half2_rn(a.x, a.y);
    __half2 h1 = __floats2half2_rn(a.z, a.w);
    __half2 h2 = __floats2half2_rn(b.x, b.y);
    __half2 h3 = __floats2half2_rn(b.z, b.w);
    uint4 o;
    o.x = *(uint32_t*)&h0; o.y = *(uint32_t*)&h1;
    o.z = *(uint32_t*)&h2; o.w = *(uint32_t*)&h3;
    *(uint4*)(d + i) = o;
}
__global__ void cvt_k(const float* __restrict__ s, __half* __restrict__ d, int n) {
    int i = (blockIdx.x * 256 + threadIdx.x) * 8;
    if (i >= n) return;
    float4 a = *(const float4*)(s + i);
    float4 b = *(const float4*)(s + i + 4);
    __half2 h0 = __floats2half2_rn(a.x, a.y);
    __half2 h1 = __floats2half2_rn(a.z, a.w);
    __half2 h2 = __floats2half2_rn(b.x, b.y);
    __half2 h3 = __floats2half2_rn(b.z, b.w);
    uint4 o;
    o.x = *(uint32_t*)&h0; o.y = *(uint32_t*)&h1;
    o.z = *(uint32_t*)&h2; o.w = *(uint32_t*)&h3;
    *(uint4*)(d + i) = o;
}

// ================= unified fp16 mma GEMM =================
// block tile 128(M) x 64(N), BK=32, 256 threads = 8 warps (4 M x 2 N),
// warp tile 32x32 (R9 proven configuration).
// MODE 0: Cf = A @ Bw^T + Res           (wo projection, fp32 out)
// MODE 1: hg = silu(X@W1^T)*(X@W3^T)    (gathered rows, half out)
// MODE 2: ymid = gate * (hg @ W2^T)     (half out)
// MODE 3: fused QKV (combined weights, half out packed)
template<int MODE>
__global__ __launch_bounds__(256, 2)
void mma_gemm(const __half* __restrict__ A, const __half* __restrict__ Bw,
              const __half* __restrict__ B3w, const float* __restrict__ Res,
              float* __restrict__ Cf, __half* __restrict__ Ch,
              int M, int N, int Kd)
{
    constexpr int STAGES = 4;
    constexpr uint32_t ASTG = 128 * 80;   // bytes (128 rows x 40 halves)
    constexpr uint32_t BSTG = 64 * 80;
    extern __shared__ char smraw[];
    uint32_t smA = smem_u32(smraw);
    uint32_t smB  = smA + STAGES * ASTG;
    uint32_t smB3 = smB + STAGES * BSTG;
    __shared__ int stok[128];

    int tid = threadIdx.x;
    int lane = tid & 31, wid = tid >> 5;
    int wm = (wid & 3) * 32, wn = (wid >> 2) * 32;
    int gq = lane >> 2, tq = lane & 3;

    int e = blockIdx.z;
    int cnt, base;
    const __half* b1p;
    const __half* b3p = nullptr;
    int n0 = blockIdx.x * 64;
    int which = 0;
    if (MODE == 0)      { cnt = M; base = 0; b1p = Bw; }
    else if (MODE == 1) { cnt = g_counts[e]; base = g_basev[e];
                          b1p = Bw  + (size_t)e * FF * DIM;
                          b3p = B3w + (size_t)e * FF * DIM; }
    else if (MODE == 2) { cnt = g_counts[e]; base = g_basev[e];
                          b1p = Bw + (size_t)e * DIM * FF; }
    else                { cnt = M; base = 0;
                          which = n0 >> 10; n0 &= 1023;
                          b1p = Bw + ((size_t)which << 10) * Kd; }
    if ((int)blockIdx.y * 128 >= cnt) return;

    const int NT = Kd >> 5;
    const int maxrow = 2 * TOK - 1;

    // ldmatrix per-lane addressing (stride 40 halves = 80B)
    uint32_t aA0 = smA + (uint32_t)((wm + (lane & 15)) * 80 + (lane >> 4) * 16);
    int lrB = (lane & 7) + ((lane >> 4) << 3);
    uint32_t lcB = ((lane >> 3) & 1) * 16;
    uint32_t aB0  = smB  + (uint32_t)((wn + lrB) * 80) + lcB;
    uint32_t aB30 = smB3 + (uint32_t)((wn + lrB) * 80) + lcB;

    for (int rt = blockIdx.y; rt * 128 < cnt; rt += gridDim.y) {
        int m0 = rt * 128;
        if (MODE == 1) {
            if (tid < 128) {
                int lr = m0 + tid;
                stok[tid] = (lr < cnt) ? g_tokl[base + lr] : -1;
            }
            __syncthreads();
        }

        auto load_tile = [&](int st, int kt) {
            int k0 = kt << 5;
#pragma unroll
            for (int i = 0; i < 2; i++) {          // A: 128 rows x 4 chunks(16B)
                int f = i * 256 + tid;
                int row = f >> 2, c = f & 3;
                uint32_t d = smA + (uint32_t)st * ASTG + (uint32_t)(row * 80 + c * 16);
                const __half* s;
                int sz = 16;
                if (MODE == 0 || MODE == 3) {
                    s = A + (size_t)(m0 + row) * Kd + k0 + c * 8;
                } else if (MODE == 1) {
                    int t = stok[row];
                    if (t < 0) { t = 0; sz = 0; }
                    s = g_xnh + (size_t)t * DIM + k0 + c * 8;
                } else {
                    int ar = base + m0 + row;
                    if (ar > maxrow) ar = maxrow;
                    s = g_hgh + (size_t)ar * FF + k0 + c * 8;
                }
                cpa16(d, s, sz);
            }
            {                                       // B: 64 rows x 4 chunks
                int row = tid >> 2, c = tid & 3;
                uint32_t off = (uint32_t)(row * 80 + c * 16);
                cpa16(smB + (uint32_t)st * BSTG + off,
                      b1p + (size_t)(n0 + row) * Kd + k0 + c * 8, 16);
                if (MODE == 1)
                    cpa16(smB3 + (uint32_t)st * BSTG + off,
                          b3p + (size_t)(n0 + row) * Kd + k0 + c * 8, 16);
            }
        };

        float acc[2][4][4] = {};
        float acc3[(MODE == 1) ? 2 : 1][(MODE == 1) ? 4 : 1][4] = {};

#pragma unroll
        for (int i = 0; i < STAGES - 1; i++) { load_tile(i, i); CPA_COMMIT(); }

        for (int kt = 0; kt < NT; kt++) {
            asm volatile("cp.async.wait_group 2;" ::: "memory");
            __syncthreads();
            int st = kt & 3;
            {
                int nst = kt + 3;
                if (nst < NT) load_tile(nst & 3, nst);
                CPA_COMMIT();
            }
            uint32_t sA = (uint32_t)st * ASTG;
            uint32_t sB = (uint32_t)st * BSTG;
#pragma unroll
            for (int kg = 0; kg < 2; kg++) {
                uint32_t af[2][4];
                LDSM4(af[0], aA0 + sA + kg * 32);
                LDSM4(af[1], aA0 + sA + 1280 + kg * 32);
                uint32_t bf[4][2];
#pragma unroll
                for (int j = 0; j < 2; j++) {
                    uint32_t t4[4];
                    LDSM4(t4, aB0 + sB + j * 1280 + kg * 32);
                    bf[2 * j][0] = t4[0]; bf[2 * j][1] = t4[1];
                    bf[2 * j + 1][0] = t4[2]; bf[2 * j + 1][1] = t4[3];
                }
                if (MODE == 1) {
                    uint32_t b3f[4][2];
#pragma unroll
                    for (int j = 0; j < 2; j++) {
                        uint32_t t4[4];
                        LDSM4(t4, aB30 + sB + j * 1280 + kg * 32);
                        b3f[2 * j][0] = t4[0]; b3f[2 * j][1] = t4[1];
                        b3f[2 * j + 1][0] = t4[2]; b3f[2 * j + 1][1] = t4[3];
                    }
#pragma unroll
                    for (int mi = 0; mi < 2; mi++)
#pragma unroll
                        for (int ni = 0; ni < 4; ni++) {
                            mma16(acc[mi][ni], af[mi], bf[ni]);
                            mma16(acc3[mi][ni], af[mi], b3f[ni]);
                        }
                } else {
#pragma unroll
                    for (int mi = 0; mi < 2; mi++)
#pragma unroll
                        for (int ni = 0; ni < 4; ni++)
                            mma16(acc[mi][ni], af[mi], bf[ni]);
                }
            }
        }

        // ---------------- epilogue ----------------
        if (MODE == 0) {
#pragma unroll
            for (int mi = 0; mi < 2; mi++) {
                int r0 = m0 + wm + mi * 16 + gq;
#pragma unroll
                for (int ni = 0; ni < 4; ni++) {
                    int c0 = n0 + wn + ni * 8 + 2 * tq;
                    float2 v0 = make_float2(acc[mi][ni][0], acc[mi][ni][1]);
                    float2 v1 = make_float2(acc[mi][ni][2], acc[mi][ni][3]);
                    float2 q0 = *(const float2*)&Res[(size_t)r0 * N + c0];
                    float2 q1 = *(const float2*)&Res[(size_t)(r0 + 8) * N + c0];
                    v0.x += q0.x; v0.y += q0.y; v1.x += q1.x; v1.y += q1.y;
                    *(float2*)&Cf[(size_t)r0 * N + c0] = v0;
                    *(float2*)&Cf[(size_t)(r0 + 8) * N + c0] = v1;
                }
            }
        } else if (MODE == 3) {
            __half* Co = Ch + (size_t)which * TOK * DIM;
#pragma unroll
            for (int mi = 0; mi < 2; mi++) {
                int r0 = m0 + wm + mi * 16 + gq;
#pragma unroll
                for (int ni = 0; ni < 4; ni++) {
                    int c0 = n0 + wn + ni * 8 + 2 * tq;
                    *(__half2*)&Co[(size_t)r0 * N + c0] =
                        __floats2half2_rn(acc[mi][ni][0], acc[mi][ni][1]);
                    *(__half2*)&Co[(size_t)(r0 + 8) * N + c0] =
                        __floats2half2_rn(acc[mi][ni][2], acc[mi][ni][3]);
                }
            }
        } else if (MODE == 1) {
#pragma unroll
            for (int mi = 0; mi < 2; mi++) {
#pragma unroll
                for (int half = 0; half < 2; half++) {
                    int rl = m0 + wm + mi * 16 + gq + half * 8;
                    if (rl < cnt) {
                        __half* op = g_hgh + (size_t)(base + rl) * FF;
#pragma unroll
                        for (int ni = 0; ni < 4; ni++) {
                            int c0 = n0 + wn + ni * 8 + 2 * tq;
                            float z0 = acc[mi][ni][half * 2];
                            float z1 = acc[mi][ni][half * 2 + 1];
                            float h0 = (z0 / (1.f + __expf(-z0))) * acc3[mi][ni][half * 2];
                            float h1 = (z1 / (1.f + __expf(-z1))) * acc3[mi][ni][half * 2 + 1];
                            *(__half2*)&op[c0] = __floats2half2_rn(h0, h1);
                        }
                    }
                }
            }
        } else {
#pragma unroll
            for (int mi = 0; mi < 2; mi++) {
#pragma unroll
                for (int half = 0; half < 2; half++) {
                    int rl = m0 + wm + mi * 16 + gq + half * 8;
                    if (rl < cnt) {
                        float gate = g_agate[base + rl];
                        __half* op = g_ymidh + (size_t)(base + rl) * DIM;
#pragma unroll
                        for (int ni = 0; ni < 4; ni++) {
                            int c0 = n0 + wn + ni * 8 + 2 * tq;
                            *(__half2*)&op[c0] =
                                __floats2half2_rn(acc[mi][ni][half * 2] * gate,
                                                  acc[mi][ni][half * 2 + 1] * gate);
                        }
                    }
                }
            }
        }
        __syncthreads();
    }
}

// ---------------- rmsnorm (exact fp32 + half copies) ----------------
__global__ void rmsnorm_k(const float* __restrict__ x, const float* __restrict__ w,
                          float* __restrict__ out, __half* __restrict__ outh) {
    int row = blockIdx.x;
    const float* xr = x + (size_t)row * DIM;
    float v[4];
    float s = 0.f;
#pragma unroll
    for (int i = 0; i < 4; i++) {
        v[i] = xr[threadIdx.x + i * 256];
        s += v[i] * v[i];
    }
    __shared__ float red[8];
#pragma unroll
    for (int o = 16; o > 0; o >>= 1) s += __shfl_xor_sync(0xffffffffu, s, o);
    if ((threadIdx.x & 31) == 0) red[threadIdx.x >> 5] = s;
    __syncthreads();
    if (threadIdx.x < 8) {
        float t = red[threadIdx.x];
#pragma unroll
        for (int o = 4; o > 0; o >>= 1) t += __shfl_xor_sync(0xffu, t, o);
        if (threadIdx.x == 0) red[0] = t;
    }
    __syncthreads();
    float scale = rsqrtf(red[0] * (1.0f / DIM) + 1e-6f);
#pragma unroll
    for (int i = 0; i < 4; i++) {
        int c = threadIdx.x + i * 256;
        float val = v[i] * scale * w[c];
        out[(size_t)row * DIM + c]  = val;
        outh[(size_t)row * DIM + c] = __float2half_rn(val);
    }
}

// ---------------- RoPE (half in/out, fp32 math) ----------------
__global__ void rope_k(__half* __restrict__ qh, __half* __restrict__ kh,
                       const float* __restrict__ fc, const float* __restrict__ fs) {
    int idx = blockIdx.x * blockDim.x + threadIdx.x;
    if (idx >= TOK * NH * (HDIM / 2)) return;
    int i = idx & 31;
    int h = (idx >> 5) & (NH - 1);
    int t = idx >> 9;
    int s = t & (SEQ - 1);
    float c = fc[s * 32 + i], sn = fs[s * 32 + i];
    size_t bse = (size_t)t * DIM + h * HDIM + 2 * i;
    float2 q2 = __half22float2(*(__half2*)&qh[bse]);
    *(__half2*)&qh[bse] = __floats2half2_rn(q2.x * c - q2.y * sn, q2.x * sn + q2.y * c);
    float2 k2 = __half22float2(*(__half2*)&kh[bse]);
    *(__half2*)&kh[bse] = __floats2half2_rn(k2.x * c - k2.y * sn, k2.x * sn + k2.y * c);
}

// ---------------- flash attention, fp16 mma, 128x64 tiles ----------------
#define FBM 128
#define FBN 64
__global__ __launch_bounds__(256, 2)
void flash_k(const __half* __restrict__ Q, const __half* __restrict__ Kp,
             const __half* __restrict__ V, __half* __restrict__ O,
             const int* __restrict__ p_causal) {
    constexpr uint32_t KVSTG = 64 * 144;          // bytes per K or V stage
    extern __shared__ char smraw[];
    __half* Qs = (__half*)smraw;                  // [128][72]
    __half* Ks = Qs + 128 * 72;                   // [2][64][72]
    __half* Vs = Ks + 2 * 64 * 72;                // [2][64][72] natural [kv][d]
    __half* Ps = Vs + 2 * 64 * 72;                // [128][72]
    float* redm = (float*)(Ps + 128 * 72);        // [2][128]
    float* reds = redm + 256;                     // [2][128]

    int qt = gridDim.x - 1 - blockIdx.x;          // heavy causal tiles first
    int h = blockIdx.y, b = blockIdx.z;
    int causal = *p_causal;
    int tid = threadIdx.x;
    int lane = tid & 31, wid = tid >> 5;
    int wm = (wid & 3) * 32;
    int side = wid >> 2;
    int wn2 = side * 32;
    int gq = lane >> 2, tq = lane & 3;
    int t0 = b * SEQ + qt * FBM;

    uint32_t sQ = smem_u32(Qs), sK = smem_u32(Ks), sV = smem_u32(Vs), sP = smem_u32(Ps);
    uint32_t aQ = sQ + (uint32_t)((wm + (lane & 15)) * 144 + (lane >> 4) * 16);
    int lrB = (lane & 7) + ((lane >> 4) << 3);
    uint32_t aK = sK + (uint32_t)((wn2 + lrB) * 144) + ((lane >> 3) & 1) * 16;
    uint32_t aP = sP + (uint32_t)((wm + (lane & 15)) * 144 + (lane >> 4) * 16);
    uint32_t aV = sV + (uint32_t)((lane & 15) * 144 + (lane >> 4) * 16);

    // Q tile: 128 rows x 8 chunks
#pragma unroll
    for (int i = 0; i < 4; i++) {
        int f = i * 256 + tid;
        int row = f >> 3, c8 = f & 7;
        cpa16(sQ + (uint32_t)(row * 144 + c8 * 16),
              Q + (size_t)(t0 + row) * DIM + h * HDIM + c8 * 8, 16);
    }

    auto load_kv = [&](int buf, int kt) {
        int k0 = b * SEQ + kt * FBN;
#pragma unroll
        for (int i = 0; i < 2; i++) {
            int f = i * 256 + tid;
            int row = f >> 3, c8 = f & 7;
            uint32_t off = (uint32_t)buf * KVSTG + (uint32_t)(row * 144 + c8 * 16);
            const __half* src = Kp + (size_t)(k0 + row) * DIM + h * HDIM + c8 * 8;
            cpa16(sK + off, src, 16);
            const __half* srcv = V + (size_t)(k0 + row) * DIM + h * HDIM + c8 * 8;
            cpa16(sV + off, srcv, 16);
        }
    };

    load_kv(0, 0);
    CPA_COMMIT();

    float m_i[2][2], l_i[2][2], oacc[2][4][4] = {};
#pragma unroll
    for (int a = 0; a < 2; a++)
#pragma unroll
        for (int c = 0; c < 2; c++) { m_i[a][c] = -1e30f; l_i[a][c] = 0.f; }

    int nkt = causal ? (2 * qt + 2) : (SEQ / FBN);
    const float scale = 0.125f;

    for (int kt = 0; kt < nkt; kt++) {
        asm volatile("cp.async.wait_group 0;" ::: "memory");
        __syncthreads();
        if (kt + 1 < nkt) { load_kv((kt + 1) & 1, kt + 1); CPA_COMMIT(); }
        uint32_t kb = (uint32_t)(kt & 1) * KVSTG;

        // S = Q @ K^T
        float sacc[2][4][4] = {};
#pragma unroll
        for (int kg = 0; kg < 4; kg++) {
            uint32_t qf[2][4];
            LDSM4(qf[0], aQ + kg * 32);
            LDSM4(qf[1], aQ + 2304 + kg * 32);
            uint32_t kf[4][2];
#pragma unroll
            for (int j = 0; j < 2; j++) {
                uint32_t t4[4];
                LDSM4(t4, aK + kb + j * 2304 + kg * 32);
                kf[2 * j][0] = t4[0]; kf[2 * j][1] = t4[1];
                kf[2 * j + 1][0] = t4[2]; kf[2 * j + 1][1] = t4[3];
            }
#pragma unroll
            for (int mi = 0; mi < 2; mi++)
#pragma unroll
                for (int ni = 0; ni < 4; ni++)
                    mma16(sacc[mi][ni], qf[mi], kf[ni]);
        }

        // scale + mask + row max
#pragma unroll
        for (int mi = 0; mi < 2; mi++) {
            int r0 = qt * FBM + wm + mi * 16 + gq;
            float h0 = -1e30f, h1 = -1e30f;
#pragma unroll
            for (int ni = 0; ni < 4; ni++) {
                int c = kt * FBN + wn2 + ni * 8 + 2 * tq;
                float* s = sacc[mi][ni];
                s[0] *= scale; s[1] *= scale; s[2] *= scale; s[3] *= scale;
                if (causal) {
                    if (c     > r0)     s[0] = -1e30f;
                    if (c + 1 > r0)     s[1] = -1e30f;
                    if (c     > r0 + 8) s[2] = -1e30f;
                    if (c + 1 > r0 + 8) s[3] = -1e30f;
                }
                h0 = fmaxf(h0, fmaxf(s[0], s[1]));
                h1 = fmaxf(h1, fmaxf(s[2], s[3]));
            }
            h0 = fmaxf(h0, __shfl_xor_sync(0xffffffffu, h0, 1));
            h0 = fmaxf(h0, __shfl_xor_sync(0xffffffffu, h0, 2));
            h1 = fmaxf(h1, __shfl_xor_sync(0xffffffffu, h1, 1));
            h1 = fmaxf(h1, __shfl_xor_sync(0xffffffffu, h1, 2));
            if (tq == 0) {
                redm[side * 128 + wm + mi * 16 + gq]     = h0;
                redm[side * 128 + wm + mi * 16 + gq + 8] = h1;
            }
        }
        __syncthreads();

        float corr[2][2];
#pragma unroll
        for (int mi = 0; mi < 2; mi++)
#pragma unroll
            for (int hf = 0; hf < 2; hf++) {
                int rl = wm + mi * 16 + gq + hf * 8;
                float mt = fmaxf(redm[rl], redm[128 + rl]);
                float mn = fmaxf(m_i[mi][hf], mt);
                corr[mi][hf] = __expf(m_i[mi][hf] - mn);
                m_i[mi][hf] = mn;
            }

        // exp + partial sums + store P (half)
        float rs[2][2] = {};
#pragma unroll
        for (int mi = 0; mi < 2; mi++) {
#pragma unroll
            for (int ni = 0; ni < 4; ni++) {
                float* s = sacc[mi][ni];
                s[0] = __expf(s[0] - m_i[mi][0]);
                s[1] = __expf(s[1] - m_i[mi][0]);
                s[2] = __expf(s[2] - m_i[mi][1]);
                s[3] = __expf(s[3] - m_i[mi][1]);
                rs[mi][0] += s[0] + s[1];
                rs[mi][1] += s[2] + s[3];
                int rloc = wm + mi * 16 + gq;
                int cloc = wn2 + ni * 8 + 2 * tq;
                *(__half2*)&Ps[rloc * 72 + cloc] = __floats2half2_rn(s[0], s[1]);
                *(__half2*)&Ps[(rloc + 8) * 72 + cloc] = __floats2half2_rn(s[2], s[3]);
            }
            rs[mi][0] += __shfl_xor_sync(0xffffffffu, rs[mi][0], 1);
            rs[mi][0] += __shfl_xor_sync(0xffffffffu, rs[mi][0], 2);
            rs[mi][1] += __shfl_xor_sync(0xffffffffu, rs[mi][1], 1);
            rs[mi][1] += __shfl_xor_sync(0xffffffffu, rs[mi][1], 2);
            if (tq == 0) {
                reds[side * 128 + wm + mi * 16 + gq]     = rs[mi][0];
                reds[side * 128 + wm + mi * 16 + gq + 8] = rs[mi][1];
            }
        }
        __syncthreads();

#pragma unroll
        for (int mi = 0; mi < 2; mi++)
#pragma unroll
            for (int hf = 0; hf < 2; hf++) {
                int rl = wm + mi * 16 + gq + hf * 8;
                l_i[mi][hf] = l_i[mi][hf] * corr[mi][hf] + reds[rl] + reds[128 + rl];
            }
#pragma unroll
        for (int mi = 0; mi < 2; mi++)
#pragma unroll
            for (int ni = 0; ni < 4; ni++) {
                oacc[mi][ni][0] *= corr[mi][0];
                oacc[mi][ni][1] *= corr[mi][0];
                oacc[mi][ni][2] *= corr[mi][1];
                oacc[mi][ni][3] *= corr[mi][1];
            }

        // O += P @ V   (V natural layout, ldmatrix.trans for B frags)
#pragma unroll
        for (int kg = 0; kg < 4; kg++) {
            uint32_t pf[2][4];
            LDSM4(pf[0], aP + kg * 32);
            LDSM4(pf[1], aP + 2304 + kg * 32);
            uint32_t vf[4][2];
#pragma unroll
            for (int j = 0; j < 2; j++) {
                uint32_t t4[4];
                LDSM4T(t4, aV + kb + kg * 2304 + (uint32_t)((wn2 + j * 16) * 2));
                vf[2 * j][0] = t4[0]; vf[2 * j][1] = t4[1];
                vf[2 * j + 1][0] = t4[2]; vf[2 * j + 1][1] = t4[3];
            }
#pragma unroll
            for (int mi = 0; mi < 2; mi++)
#pragma unroll
                for (int ni = 0; ni < 4; ni++)
                    mma16(oacc[mi][ni], pf[mi], vf[ni]);
        }
    }

    // normalize + write half
#pragma unroll
    for (int mi = 0; mi < 2; mi++) {
        float inv0 = 1.0f / l_i[mi][0];
        float inv1 = 1.0f / l_i[mi][1];
        int rl = t0 + wm + mi * 16 + gq;
#pragma unroll
        for (int ni = 0; ni < 4; ni++) {
            int d0 = h * HDIM + wn2 + ni * 8 + 2 * tq;
            *(__half2*)&O[(size_t)rl * DIM + d0] =
                __floats2half2_rn(oacc[mi][ni][0] * inv0, oacc[mi][ni][1] * inv0);
            *(__half2*)&O[(size_t)(rl + 8) * DIM + d0] =
                __floats2half2_rn(oacc[mi][ni][2] * inv1, oacc[mi][ni][3] * inv1);
        }
    }
}

// ---------------- routing ----------------
__global__ void reset_k() { if (threadIdx.x < NE) g_counts[threadIdx.x] = 0; }

__global__ void router_k(const float* __restrict__ rw, const float* __restrict__ rb) {
    int t = blockIdx.x;
    int wid = threadIdx.x >> 5, lane = threadIdx.x & 31;
    const float* x = g_xn + (size_t)t * DIM;
    const float* w = rw + (size_t)wid * DIM;
    float s = 0.f;
    for (int j = lane; j < DIM; j += 32) s += x[j] * w[j];
#pragma unroll
    for (int o = 16; o > 0; o >>= 1) s += __shfl_xor_sync(0xffffffffu, s, o);
    __shared__ float lg[NE];
    if (lane == 0) lg[wid] = s + rb[wid];
    __syncthreads();
    if (threadIdx.x == 0) {
        float v0 = -1e30f; int i0 = 0;
#pragma unroll
        for (int e = 0; e < NE; e++) if (lg[e] > v0) { v0 = lg[e]; i0 = e; }
        float v1 = -1e30f; int i1 = 0;
#pragma unroll
        for (int e = 0; e < NE; e++) if (e != i0 && lg[e] > v1) { v1 = lg[e]; i1 = e; }
        float tt = __expf(v1 - v0);
        float g0 = 1.f / (1.f + tt);
        float g1 = tt / (1.f + tt);
        g_texp[2 * t] = i0;  g_texp[2 * t + 1] = i1;
        g_tgate[2 * t] = g0; g_tgate[2 * t + 1] = g1;
        atomicAdd(&g_counts[i0], 1);
        atomicAdd(&g_counts[i1], 1);
    }
}

__global__ void prefix_k() {
    int b = 0;
    for (int e = 0; e < NE; e++) { g_basev[e] = b; g_cursor[e] = b; b += g_counts[e]; }
    g_basev[NE] = b;
}

__global__ void scatter_k() {
    int t = blockIdx.x * blockDim.x + threadIdx.x;
    if (t >= TOK) return;
#pragma unroll
    for (int r = 0; r < 2; r++) {
        int e = g_texp[2 * t + r];
        int pos = atomicAdd(&g_cursor[e], 1);
        g_tokl[pos] = t;
        g_agate[pos] = g_tgate[2 * t + r];
        g_slot[2 * t + r] = pos;
    }
}

// ---------------- final combine: out += y(slot0) + y(slot1), 8 elems/thread ----------------
__global__ void combine_k(float* __restrict__ out) {
    int i8 = (blockIdx.x * 256 + threadIdx.x) * 8;   // over TOK*DIM
    int t = i8 >> 10;
    int d = i8 & 1023;
    int s0 = g_slot[2 * t], s1 = g_slot[2 * t + 1];
    const __half* y0 = g_ymidh + (size_t)s0 * DIM + d;
    const __half* y1 = g_ymidh + (size_t)s1 * DIM + d;
    uint4 a = *(const uint4*)y0;
    uint4 b = *(const uint4*)y1;
    float4 o0 = *(float4*)(out + i8);
    float4 o1 = *(float4*)(out + i8 + 4);
    float2 p;
    p = __half22float2(*(__half2*)&a.x); o0.x += p.x; o0.y += p.y;
    p = __half22float2(*(__half2*)&a.y); o0.z += p.x; o0.w += p.y;
    p = __half22float2(*(__half2*)&a.z); o1.x += p.x; o1.y += p.y;
    p = __half22float2(*(__half2*)&a.w); o1.z += p.x; o1.w += p.y;
    p = __half22float2(*(__half2*)&b.x); o0.x += p.x; o0.y += p.y;
    p = __half22float2(*(__half2*)&b.y); o0.z += p.x; o0.w += p.y;
    p = __half22float2(*(__half2*)&b.z); o1.x += p.x; o1.y += p.y;
    p = __half22float2(*(__half2*)&b.w); o1.z += p.x; o1.w += p.y;
    *(float4*)(out + i8)     = o0;
    *(float4*)(out + i8 + 4) = o1;
}

// ---------------- launch ----------------
extern "C" void kernel_launch(void* const* d_in, const int* in_sizes, int n_in,
                              void* d_out, int out_size) {
    const float* q    = (const float*)d_in[0];
    const float* fc   = (const float*)d_in[3];
    const float* fs   = (const float*)d_in[4];
    const float* attw = (const float*)d_in[5];
    const float* ffnw = (const float*)d_in[6];
    const float* wq   = (const float*)d_in[7];
    const float* wk   = (const float*)d_in[8];
    const float* wv   = (const float*)d_in[9];
    const float* wo   = (const float*)d_in[10];
    const float* rw   = (const float*)d_in[11];
    const float* rb   = (const float*)d_in[12];
    const float* w1   = (const float*)d_in[13];
    const float* w2   = (const float*)d_in[14];
    const float* w3   = (const float*)d_in[15];
    const int*   pc   = (const int*)d_in[16];
    float* out = (float*)d_out;

    float *p_xn;
    __half *p_xnh, *p_qkvh, *p_attnh;
    __half *p_wqkvh, *p_woh, *p_w1h, *p_w3h, *p_w2h;
    cudaGetSymbolAddress((void**)&p_xn, g_xn);
    cudaGetSymbolAddress((void**)&p_xnh, g_xnh);
    cudaGetSymbolAddress((void**)&p_qkvh, g_qkvh);
    cudaGetSymbolAddress((void**)&p_attnh, g_attnh);
    cudaGetSymbolAddress((void**)&p_wqkvh, g_wqkvh);
    cudaGetSymbolAddress((void**)&p_woh, g_woh);
    cudaGetSymbolAddress((void**)&p_w1h, g_w1h);
    cudaGetSymbolAddress((void**)&p_w3h, g_w3h);
    cudaGetSymbolAddress((void**)&p_w2h, g_w2h);

    const int SMEM_G  = 4 * (128 * 80) + 4 * (64 * 80) + 4 * (64 * 80);  // 81920 (mode1 max)
    const int SMEM_FL = (128 * 72 + 2 * 64 * 72 + 2 * 64 * 72 + 128 * 72) * 2 + 512 * 4;
    cudaFuncSetAttribute(mma_gemm<0>, cudaFuncAttributeMaxDynamicSharedMemorySize, SMEM_G);
    cudaFuncSetAttribute(mma_gemm<1>, cudaFuncAttributeMaxDynamicSharedMemorySize, SMEM_G);
    cudaFuncSetAttribute(mma_gemm<2>, cudaFuncAttributeMaxDynamicSharedMemorySize, SMEM_G);
    cudaFuncSetAttribute(mma_gemm<3>, cudaFuncAttributeMaxDynamicSharedMemorySize, SMEM_G);
    cudaFuncSetAttribute(flash_k, cudaFuncAttributeMaxDynamicSharedMemorySize, SMEM_FL);

    // 0. convert weights to fp16 (per-launch, deterministic)
    const int WQN = DIM * DIM;              // 1048576
    const int WEN = NE * FF * DIM;          // 33554432
    cvt3_k<<<dim3(WQN / 8 / 256, 3), 256>>>(wq, wk, wv,
        p_wqkvh, p_wqkvh + (size_t)WQN, p_wqkvh + (size_t)2 * WQN, WQN);
    cvt_k<<<WQN / 8 / 256, 256>>>(wo, p_woh, WQN);
    cvt3_k<<<dim3(WEN / 8 / 256, 3), 256>>>(w1, w3, w2, p_w1h, p_w3h, p_w2h, WEN);

    // 1. attention-input rmsnorm
    rmsnorm_k<<<TOK, 256>>>(q, attw, p_xn, p_xnh);

    // 2. fused QKV projection (fp16 mma)
    mma_gemm<3><<<dim3(3 * DIM / 64, TOK / 128), 256, SMEM_G>>>(
        p_xnh, p_wqkvh, nullptr, nullptr, nullptr, p_qkvh, TOK, DIM, DIM);

    // 3. RoPE on q,k halves
    rope_k<<<(TOK * NH * 32 + 255) / 256, 256>>>(p_qkvh, p_qkvh + (size_t)TOK * DIM, fc, fs);

    // 4. flash attention (fp16 mma)
    dim3 gfa(SEQ / 128, NH, 4);
    flash_k<<<gfa, 256, SMEM_FL>>>(p_qkvh, p_qkvh + (size_t)TOK * DIM,
                                   p_qkvh + (size_t)2 * TOK * DIM, p_attnh, pc);

    // 5. output projection + residual (fp32 out)
    mma_gemm<0><<<dim3(DIM / 64, TOK / 128), 256, SMEM_G>>>(
        p_attnh, p_woh, nullptr, q, out, nullptr, TOK, DIM, DIM);

    // 6. ffn rmsnorm (exact for router, half for GEMMs)
    rmsnorm_k<<<TOK, 256>>>(out, ffnw, p_xn, p_xnh);

    // 7. routing (exact fp32)
    reset_k<<<1, 32>>>();
    router_k<<<TOK, 256>>>(rw, rb);
    prefix_k<<<1, 1>>>();
    scatter_k<<<TOK / 256, 256>>>();

    // 8. MoE grouped GEMMs (fp16 mma)
    mma_gemm<1><<<dim3(FF / 64, 8, NE), 256, SMEM_G>>>(
        nullptr, p_w1h, p_w3h, nullptr, nullptr, nullptr, 0, FF, DIM);
    mma_gemm<2><<<dim3(DIM / 64, 8, NE), 256, SMEM_G>>>(
        nullptr, p_w2h, nullptr, nullptr, nullptr, nullptr, 0, DIM, FF);

    // 9. combine
    combine_k<<<TOK * DIM / 8 / 256, 256>>>(out);
}